// round 16
// baseline (speedup 1.0000x reference)
#include <cuda_runtime.h>
#include <cuda_fp16.h>

#define NN 100000
#define EE 1200000
#define D  64
#define GR 128     // X rows per GEMM block
#define SCH 1024   // scan chunk (elements per scan block)

// Scratch (device globals: no allocation allowed in kernel_launch).
// g_counts/g_flag are zero at load; gather_kernel re-zeroes them every launch.
__device__ float  g_q[(size_t)NN * D];
__device__ __half g_kh[(size_t)NN * D];   // K in fp16 (logits only)
__device__ __half g_vh[(size_t)NN * D];   // V in fp16
__device__ float  g_skip[(size_t)NN * D];
__device__ int    g_counts[NN];
__device__ int    g_cursor[NN];    // scan output; after scatter = segment END
__device__ int    g_agg[128];      // per-chunk aggregates (lookback scan)
__device__ int    g_flag[128];     // publish flags
__device__ int    g_sorted_src[EE + 16];

// ---------------------------------------------------------------------------
// packed f32x2 helpers (Blackwell sm_100+)
// ---------------------------------------------------------------------------
__device__ __forceinline__ unsigned long long dup_f32x2(float x) {
    unsigned long long r;
    asm("mov.b64 %0, {%1, %1};" : "=l"(r) : "f"(x));
    return r;
}
__device__ __forceinline__ void fma_f32x2(unsigned long long& acc,
                                          unsigned long long a,
                                          unsigned long long b) {
    asm("fma.rn.f32x2 %0, %1, %2, %3;" : "=l"(acc) : "l"(a), "l"(b), "l"(acc));
}
__device__ __forceinline__ float2 unpack_f32x2(unsigned long long p) {
    float lo, hi;
    asm("mov.b64 {%0, %1}, %2;" : "=f"(lo), "=f"(hi) : "l"(p));
    return make_float2(lo, hi);
}

// ---------------------------------------------------------------------------
// K_GEMM: blockIdx.y in {0..3} selects W/b/Y (q,k,v,skip).
// y==1 (K) and y==2 (V) store fp16; q and skip store fp32.
// ---------------------------------------------------------------------------
__global__ void __launch_bounds__(128) gemm_one(
    const float* __restrict__ X,
    const float* __restrict__ Wq, const float* __restrict__ bq,
    const float* __restrict__ Wk, const float* __restrict__ bk,
    const float* __restrict__ Wv, const float* __restrict__ bv,
    const float* __restrict__ Ws, const float* __restrict__ bs,
    float* __restrict__ Yq, __half* __restrict__ Ykh,
    __half* __restrict__ Yvh, float* __restrict__ Ys, int n) {
    __shared__ float xsT[D][GR];   // [k][row]
    __shared__ float ws[D][D];

    int tid  = threadIdx.x;
    int row0 = blockIdx.x * GR;

    const float* W; const float* B;
    switch (blockIdx.y) {
        case 0:  W = Wq; B = bq; break;
        case 1:  W = Wk; B = bk; break;
        case 2:  W = Wv; B = bv; break;
        default: W = Ws; B = bs; break;
    }

    for (int i = tid; i < D * D / 4; i += 128)
        ((float4*)ws)[i] = ((const float4*)W)[i];

    {
        int r = tid;
        bool ok = (row0 + r < n);
#pragma unroll
        for (int c4 = 0; c4 < D / 4; c4++) {
            float4 v = make_float4(0.f, 0.f, 0.f, 0.f);
            if (ok)
                v = ((const float4*)X)[(size_t)(row0 + r) * (D / 4) + c4];
            xsT[c4 * 4 + 0][r] = v.x;
            xsT[c4 * 4 + 1][r] = v.y;
            xsT[c4 * 4 + 2][r] = v.z;
            xsT[c4 * 4 + 3][r] = v.w;
        }
    }
    __syncthreads();

    int tr = (tid >> 3) * 8;  // 0..120
    int tc = (tid & 7) * 8;   // 0..56

    unsigned long long acc[8][4];
#pragma unroll
    for (int r = 0; r < 8; r++)
#pragma unroll
        for (int c = 0; c < 4; c++) acc[r][c] = 0ull;

#pragma unroll 4
    for (int kk = 0; kk < D; kk++) {
        float4 xa = *(const float4*)&xsT[kk][tr];
        float4 xb = *(const float4*)&xsT[kk][tr + 4];
        ulonglong2 wA = *(const ulonglong2*)&ws[kk][tc];
        ulonglong2 wB = *(const ulonglong2*)&ws[kk][tc + 4];
        unsigned long long xd[8];
        xd[0] = dup_f32x2(xa.x); xd[1] = dup_f32x2(xa.y);
        xd[2] = dup_f32x2(xa.z); xd[3] = dup_f32x2(xa.w);
        xd[4] = dup_f32x2(xb.x); xd[5] = dup_f32x2(xb.y);
        xd[6] = dup_f32x2(xb.z); xd[7] = dup_f32x2(xb.w);
#pragma unroll
        for (int r = 0; r < 8; r++) {
            fma_f32x2(acc[r][0], xd[r], wA.x);
            fma_f32x2(acc[r][1], xd[r], wA.y);
            fma_f32x2(acc[r][2], xd[r], wB.x);
            fma_f32x2(acc[r][3], xd[r], wB.y);
        }
    }

    float4 bA = ((const float4*)B)[tc / 4];
    float4 bB = ((const float4*)B)[tc / 4 + 1];
    int y = blockIdx.y;
#pragma unroll
    for (int r = 0; r < 8; r++) {
        int grow = row0 + tr + r;
        if (grow < n) {
            float2 p0 = unpack_f32x2(acc[r][0]);
            float2 p1 = unpack_f32x2(acc[r][1]);
            float2 p2 = unpack_f32x2(acc[r][2]);
            float2 p3 = unpack_f32x2(acc[r][3]);
            float4 o0 = make_float4(p0.x + bA.x, p0.y + bA.y,
                                    p1.x + bA.z, p1.y + bA.w);
            float4 o1 = make_float4(p2.x + bB.x, p2.y + bB.y,
                                    p3.x + bB.z, p3.y + bB.w);
            if (y == 1 || y == 2) {
                __half2 ph[4];
                ph[0] = __floats2half2_rn(o0.x, o0.y);
                ph[1] = __floats2half2_rn(o0.z, o0.w);
                ph[2] = __floats2half2_rn(o1.x, o1.y);
                ph[3] = __floats2half2_rn(o1.z, o1.w);
                __half* Yh = (y == 1) ? Ykh : Yvh;
                *((uint4*)(Yh + (size_t)grow * D + tc)) = *(const uint4*)ph;
            } else {
                float* Y = (y == 0) ? Yq : Ys;
                ((float4*)(Y + (size_t)grow * D + tc))[0] = o0;
                ((float4*)(Y + (size_t)grow * D + tc))[1] = o1;
            }
        }
    }
}

// ---------------------------------------------------------------------------
// CSR build: histogram -> fused decoupled-lookback scan -> scatter
// ---------------------------------------------------------------------------
__global__ void hist_kernel(const int* __restrict__ ei, int E) {
    const int4* d4 = (const int4*)(ei + E);
    int n4 = E >> 2;
    for (int i = blockIdx.x * blockDim.x + threadIdx.x; i < n4;
         i += gridDim.x * blockDim.x) {
        int4 v = d4[i];
        atomicAdd(&g_counts[v.x], 1);
        atomicAdd(&g_counts[v.y], 1);
        atomicAdd(&g_counts[v.z], 1);
        atomicAdd(&g_counts[v.w], 1);
    }
    int t = blockIdx.x * blockDim.x + threadIdx.x;
    if (t < (E & 3)) atomicAdd(&g_counts[ei[E + (n4 << 2) + t]], 1);
}

// single-kernel exclusive scan over g_counts -> g_cursor (decoupled lookback)
__global__ void __launch_bounds__(256) scan_fused(int n, int nblk) {
    __shared__ int sdata[256];
    int b    = blockIdx.x;
    int t    = threadIdx.x;
    int base = b * SCH + t * 4;

    int v[4];
#pragma unroll
    for (int j = 0; j < 4; j++)
        v[j] = (base + j < n) ? g_counts[base + j] : 0;
    int tsum = v[0] + v[1] + v[2] + v[3];

    sdata[t] = tsum;
    __syncthreads();
    for (int off = 1; off < 256; off <<= 1) {
        int x = (t >= off) ? sdata[t - off] : 0;
        __syncthreads();
        sdata[t] += x;
        __syncthreads();
    }
    int excl  = sdata[t] - tsum;
    int total = sdata[255];

    if (t == 0) {
        g_agg[b] = total;
        __threadfence();
        atomicExch(&g_flag[b], 1);
    }

    int mine = 0;
    if (t < b) {
        while (atomicAdd(&g_flag[t], 0) == 0) {}
        __threadfence();
        mine = g_agg[t];
    }
    __syncthreads();
    sdata[t] = mine;
    __syncthreads();
    for (int off = 128; off > 0; off >>= 1) {
        if (t < off) sdata[t] += sdata[t + off];
        __syncthreads();
    }
    int cbase = sdata[0];

    int run = excl + cbase;
#pragma unroll
    for (int j = 0; j < 4; j++) {
        if (base + j < n) g_cursor[base + j] = run;
        run += v[j];
    }
}

__global__ void scatter_kernel(const int* __restrict__ ei, int E) {
    const int4* s4 = (const int4*)ei;
    const int4* d4 = (const int4*)(ei + E);
    int n4 = E >> 2;
    for (int i = blockIdx.x * blockDim.x + threadIdx.x; i < n4;
         i += gridDim.x * blockDim.x) {
        int4 s = s4[i];
        int4 d = d4[i];
        g_sorted_src[atomicAdd(&g_cursor[d.x], 1)] = s.x;
        g_sorted_src[atomicAdd(&g_cursor[d.y], 1)] = s.y;
        g_sorted_src[atomicAdd(&g_cursor[d.z], 1)] = s.z;
        g_sorted_src[atomicAdd(&g_cursor[d.w], 1)] = s.w;
    }
    int t = blockIdx.x * blockDim.x + threadIdx.x;
    if (t < (E & 3)) {
        int e = (n4 << 2) + t;
        g_sorted_src[atomicAdd(&g_cursor[ei[E + e]], 1)] = ei[e];
    }
}

// ---------------------------------------------------------------------------
// K_GATHER: warp-per-destination, QUARTER-WARP (8 lanes) per edge.
// Lane = (qid, ql): qid in 0..3 selects the edge of the group, ql in 0..7
// selects a 16B chunk (8 fp16) of the row -> k/v are one LDG.128 each,
// dot-reduce is 3 shuffles over the 8-lane group, one __expf serves 4 edges.
// beg = cursor[dst-1] (scatter leaves cursor[dst] == segment end).
// Also re-zeroes g_counts/g_flag for the next graph replay (replaces tail).
// ---------------------------------------------------------------------------
__global__ void __launch_bounds__(256) gather_kernel(
    float* __restrict__ out, int n) {
    int warp = (blockIdx.x * blockDim.x + threadIdx.x) >> 5;
    int lane = threadIdx.x & 31;
    if (warp >= n) return;

    int dst = warp;
    int end = g_cursor[dst];
    int beg = (dst > 0) ? g_cursor[dst - 1] : 0;
    int qid = lane >> 3;   // edge slot within group of 4
    int ql  = lane & 7;    // 16B chunk within row

    // q chunk: 8 floats, pre-scaled by 1/sqrt(64)
    float qr[8];
    {
        const float4* qp = (const float4*)(g_q + (size_t)dst * D + ql * 8);
        float4 a = qp[0], b = qp[1];
        qr[0] = a.x * 0.125f; qr[1] = a.y * 0.125f;
        qr[2] = a.z * 0.125f; qr[3] = a.w * 0.125f;
        qr[4] = b.x * 0.125f; qr[5] = b.y * 0.125f;
        qr[6] = b.z * 0.125f; qr[7] = b.w * 0.125f;
    }

    float acc[8];
#pragma unroll
    for (int j = 0; j < 8; j++) acc[j] = 0.f;
    float s = 0.f;

#pragma unroll 2
    for (int i = beg; i < end; i += 4) {
        int  e     = i + qid;
        bool valid = (e < end);
        int  src   = valid ? g_sorted_src[e] : 0;   // row 0 stays L1-hot

        uint4 kr = *((const uint4*)(g_kh + (size_t)src * D) + ql);
        uint4 vr = *((const uint4*)(g_vh + (size_t)src * D) + ql);

        const __half2* kh2 = (const __half2*)&kr;
        float d = 0.f;
#pragma unroll
        for (int j = 0; j < 4; j++) {
            float2 f = __half22float2(kh2[j]);
            d = fmaf(qr[2 * j], f.x, d);
            d = fmaf(qr[2 * j + 1], f.y, d);
        }
        d += __shfl_xor_sync(0xffffffffu, d, 1);
        d += __shfl_xor_sync(0xffffffffu, d, 2);
        d += __shfl_xor_sync(0xffffffffu, d, 4);

        float ex = valid ? __expf(d) : 0.f;

        const __half2* vh2 = (const __half2*)&vr;
#pragma unroll
        for (int j = 0; j < 4; j++) {
            float2 f = __half22float2(vh2[j]);
            acc[2 * j]     = fmaf(ex, f.x, acc[2 * j]);
            acc[2 * j + 1] = fmaf(ex, f.y, acc[2 * j + 1]);
        }
        s += ex;
    }

    // combine the 4 quarter-warps (lanes with equal ql)
#pragma unroll
    for (int j = 0; j < 8; j++) {
        acc[j] += __shfl_xor_sync(0xffffffffu, acc[j], 8);
        acc[j] += __shfl_xor_sync(0xffffffffu, acc[j], 16);
    }
    s += __shfl_xor_sync(0xffffffffu, s, 8);
    s += __shfl_xor_sync(0xffffffffu, s, 16);

    float r = 1.0f / (s + 1e-16f);
    if (qid == 0) {   // lanes 0..7, chunk ql == lane
        const float4* sp = (const float4*)(g_skip + (size_t)dst * D + ql * 8);
        float4 s0 = sp[0], s1 = sp[1];
        float4 o0 = make_float4(fmaf(acc[0], r, s0.x), fmaf(acc[1], r, s0.y),
                                fmaf(acc[2], r, s0.z), fmaf(acc[3], r, s0.w));
        float4 o1 = make_float4(fmaf(acc[4], r, s1.x), fmaf(acc[5], r, s1.y),
                                fmaf(acc[6], r, s1.z), fmaf(acc[7], r, s1.w));
        float4* op = (float4*)(out + (size_t)dst * D + ql * 8);
        op[0] = o0;
        op[1] = o1;
    }

    // restore zeroed scratch for the next replay
    if (lane == 0) g_counts[dst] = 0;
    if (lane == 1 && dst < 128) g_flag[dst] = 0;
}

// ---------------------------------------------------------------------------
extern "C" void kernel_launch(void* const* d_in, const int* in_sizes, int n_in,
                              void* d_out, int out_size) {
    const float* x  = (const float*)d_in[0];
    const int*   ei = (const int*)d_in[1];   // int64 in ref -> delivered int32
    // d_in[2] = edge_type (unused by reference)
    const float* Wq = (const float*)d_in[3];
    const float* bq = (const float*)d_in[4];
    const float* Wk = (const float*)d_in[5];
    const float* bk = (const float*)d_in[6];
    const float* Wv = (const float*)d_in[7];
    const float* bv = (const float*)d_in[8];
    const float* Ws = (const float*)d_in[9];
    const float* bs = (const float*)d_in[10];
    float* out = (float*)d_out;

    int n = in_sizes[0] / D;   // 100000
    int E = in_sizes[2];       // 1200000
    if (n > NN) n = NN;
    if (E > EE) E = EE;

    float *gq, *gsk;
    __half *gkh, *gvh;
    cudaGetSymbolAddress((void**)&gq,  g_q);
    cudaGetSymbolAddress((void**)&gkh, g_kh);
    cudaGetSymbolAddress((void**)&gvh, g_vh);
    cudaGetSymbolAddress((void**)&gsk, g_skip);

    int nblk = (n + SCH - 1) / SCH;

    static cudaStream_t s_side = nullptr;
    static cudaEvent_t  ev_fork = nullptr, ev_join = nullptr;
    if (s_side == nullptr) {
        cudaStreamCreateWithFlags(&s_side, cudaStreamNonBlocking);
        cudaEventCreateWithFlags(&ev_fork, cudaEventDisableTiming);
        cudaEventCreateWithFlags(&ev_join, cudaEventDisableTiming);
    }

    // ---- GEMM on side stream, concurrent with CSR build ----
    cudaEventRecord(ev_fork, 0);
    cudaStreamWaitEvent(s_side, ev_fork, 0);
    {
        dim3 grid((n + GR - 1) / GR, 4);
        gemm_one<<<grid, 128, 0, s_side>>>(x, Wq, bq, Wk, bk, Wv, bv, Ws, bs,
                                           gq, gkh, gvh, gsk, n);
    }
    cudaEventRecord(ev_join, s_side);

    // ---- CSR build on default stream (counts pre-zeroed) ----
    hist_kernel<<<(E / 4 + 255) / 256, 256>>>(ei, E);
    scan_fused<<<nblk, 256>>>(n, nblk);
    scatter_kernel<<<(E / 4 + 255) / 256, 256>>>(ei, E);

    // ---- gather (after join); also re-zeroes scratch ----
    cudaStreamWaitEvent(0, ev_join, 0);
    {
        int warps_per_block = 8;
        int blocks = (n + warps_per_block - 1) / warps_per_block;
        gather_kernel<<<blocks, 256>>>(out, n);
    }
}

// round 17
// speedup vs baseline: 1.0600x; 1.0600x over previous
#include <cuda_runtime.h>
#include <cuda_fp16.h>

#define NN 100000
#define EE 1200000
#define D  64
#define GR 128     // X rows per GEMM block
#define SCH 1024   // scan chunk (elements per scan block)

// Scratch (device globals: no allocation allowed in kernel_launch).
// g_counts/g_flag are zero at load; gather_kernel re-zeroes them every launch.
__device__ float  g_q[(size_t)NN * D];
__device__ __half g_kh[(size_t)NN * D];   // K in fp16 (logits only)
__device__ __half g_vh[(size_t)NN * D];   // V in fp16
__device__ float  g_skip[(size_t)NN * D];
__device__ int    g_counts[NN];
__device__ int    g_cursor[NN];    // scan output; after scatter = segment END
__device__ int    g_agg[128];      // per-chunk aggregates (lookback scan)
__device__ int    g_flag[128];     // publish flags
__device__ int    g_sorted_src[EE + 16];

// ---------------------------------------------------------------------------
// packed f32x2 helpers (Blackwell sm_100+)
// ---------------------------------------------------------------------------
__device__ __forceinline__ unsigned long long dup_f32x2(float x) {
    unsigned long long r;
    asm("mov.b64 %0, {%1, %1};" : "=l"(r) : "f"(x));
    return r;
}
__device__ __forceinline__ void fma_f32x2(unsigned long long& acc,
                                          unsigned long long a,
                                          unsigned long long b) {
    asm("fma.rn.f32x2 %0, %1, %2, %3;" : "=l"(acc) : "l"(a), "l"(b), "l"(acc));
}
__device__ __forceinline__ float2 unpack_f32x2(unsigned long long p) {
    float lo, hi;
    asm("mov.b64 {%0, %1}, %2;" : "=f"(lo), "=f"(hi) : "l"(p));
    return make_float2(lo, hi);
}

// ---------------------------------------------------------------------------
// K_GEMM: blockIdx.y in {0..3} selects W/b/Y (q,k,v,skip).
// y==1 (K) and y==2 (V) store fp16; q and skip store fp32.
// ---------------------------------------------------------------------------
__global__ void __launch_bounds__(128) gemm_one(
    const float* __restrict__ X,
    const float* __restrict__ Wq, const float* __restrict__ bq,
    const float* __restrict__ Wk, const float* __restrict__ bk,
    const float* __restrict__ Wv, const float* __restrict__ bv,
    const float* __restrict__ Ws, const float* __restrict__ bs,
    float* __restrict__ Yq, __half* __restrict__ Ykh,
    __half* __restrict__ Yvh, float* __restrict__ Ys, int n) {
    __shared__ float xsT[D][GR];   // [k][row]
    __shared__ float ws[D][D];

    int tid  = threadIdx.x;
    int row0 = blockIdx.x * GR;

    const float* W; const float* B;
    switch (blockIdx.y) {
        case 0:  W = Wq; B = bq; break;
        case 1:  W = Wk; B = bk; break;
        case 2:  W = Wv; B = bv; break;
        default: W = Ws; B = bs; break;
    }

    for (int i = tid; i < D * D / 4; i += 128)
        ((float4*)ws)[i] = ((const float4*)W)[i];

    {
        int r = tid;
        bool ok = (row0 + r < n);
#pragma unroll
        for (int c4 = 0; c4 < D / 4; c4++) {
            float4 v = make_float4(0.f, 0.f, 0.f, 0.f);
            if (ok)
                v = ((const float4*)X)[(size_t)(row0 + r) * (D / 4) + c4];
            xsT[c4 * 4 + 0][r] = v.x;
            xsT[c4 * 4 + 1][r] = v.y;
            xsT[c4 * 4 + 2][r] = v.z;
            xsT[c4 * 4 + 3][r] = v.w;
        }
    }
    __syncthreads();

    int tr = (tid >> 3) * 8;  // 0..120
    int tc = (tid & 7) * 8;   // 0..56

    unsigned long long acc[8][4];
#pragma unroll
    for (int r = 0; r < 8; r++)
#pragma unroll
        for (int c = 0; c < 4; c++) acc[r][c] = 0ull;

#pragma unroll 4
    for (int kk = 0; kk < D; kk++) {
        float4 xa = *(const float4*)&xsT[kk][tr];
        float4 xb = *(const float4*)&xsT[kk][tr + 4];
        ulonglong2 wA = *(const ulonglong2*)&ws[kk][tc];
        ulonglong2 wB = *(const ulonglong2*)&ws[kk][tc + 4];
        unsigned long long xd[8];
        xd[0] = dup_f32x2(xa.x); xd[1] = dup_f32x2(xa.y);
        xd[2] = dup_f32x2(xa.z); xd[3] = dup_f32x2(xa.w);
        xd[4] = dup_f32x2(xb.x); xd[5] = dup_f32x2(xb.y);
        xd[6] = dup_f32x2(xb.z); xd[7] = dup_f32x2(xb.w);
#pragma unroll
        for (int r = 0; r < 8; r++) {
            fma_f32x2(acc[r][0], xd[r], wA.x);
            fma_f32x2(acc[r][1], xd[r], wA.y);
            fma_f32x2(acc[r][2], xd[r], wB.x);
            fma_f32x2(acc[r][3], xd[r], wB.y);
        }
    }

    float4 bA = ((const float4*)B)[tc / 4];
    float4 bB = ((const float4*)B)[tc / 4 + 1];
    int y = blockIdx.y;
#pragma unroll
    for (int r = 0; r < 8; r++) {
        int grow = row0 + tr + r;
        if (grow < n) {
            float2 p0 = unpack_f32x2(acc[r][0]);
            float2 p1 = unpack_f32x2(acc[r][1]);
            float2 p2 = unpack_f32x2(acc[r][2]);
            float2 p3 = unpack_f32x2(acc[r][3]);
            float4 o0 = make_float4(p0.x + bA.x, p0.y + bA.y,
                                    p1.x + bA.z, p1.y + bA.w);
            float4 o1 = make_float4(p2.x + bB.x, p2.y + bB.y,
                                    p3.x + bB.z, p3.y + bB.w);
            if (y == 1 || y == 2) {
                __half2 ph[4];
                ph[0] = __floats2half2_rn(o0.x, o0.y);
                ph[1] = __floats2half2_rn(o0.z, o0.w);
                ph[2] = __floats2half2_rn(o1.x, o1.y);
                ph[3] = __floats2half2_rn(o1.z, o1.w);
                __half* Yh = (y == 1) ? Ykh : Yvh;
                *((uint4*)(Yh + (size_t)grow * D + tc)) = *(const uint4*)ph;
            } else {
                float* Y = (y == 0) ? Yq : Ys;
                ((float4*)(Y + (size_t)grow * D + tc))[0] = o0;
                ((float4*)(Y + (size_t)grow * D + tc))[1] = o1;
            }
        }
    }
}

// ---------------------------------------------------------------------------
// CSR build: histogram -> fused decoupled-lookback scan -> scatter
// ---------------------------------------------------------------------------
__global__ void hist_kernel(const int* __restrict__ ei, int E) {
    const int4* d4 = (const int4*)(ei + E);
    int n4 = E >> 2;
    for (int i = blockIdx.x * blockDim.x + threadIdx.x; i < n4;
         i += gridDim.x * blockDim.x) {
        int4 v = d4[i];
        atomicAdd(&g_counts[v.x], 1);
        atomicAdd(&g_counts[v.y], 1);
        atomicAdd(&g_counts[v.z], 1);
        atomicAdd(&g_counts[v.w], 1);
    }
    int t = blockIdx.x * blockDim.x + threadIdx.x;
    if (t < (E & 3)) atomicAdd(&g_counts[ei[E + (n4 << 2) + t]], 1);
}

// single-kernel exclusive scan over g_counts -> g_cursor (decoupled lookback)
__global__ void __launch_bounds__(256) scan_fused(int n, int nblk) {
    __shared__ int sdata[256];
    int b    = blockIdx.x;
    int t    = threadIdx.x;
    int base = b * SCH + t * 4;

    int v[4];
#pragma unroll
    for (int j = 0; j < 4; j++)
        v[j] = (base + j < n) ? g_counts[base + j] : 0;
    int tsum = v[0] + v[1] + v[2] + v[3];

    sdata[t] = tsum;
    __syncthreads();
    for (int off = 1; off < 256; off <<= 1) {
        int x = (t >= off) ? sdata[t - off] : 0;
        __syncthreads();
        sdata[t] += x;
        __syncthreads();
    }
    int excl  = sdata[t] - tsum;
    int total = sdata[255];

    if (t == 0) {
        g_agg[b] = total;
        __threadfence();
        atomicExch(&g_flag[b], 1);
    }

    int mine = 0;
    if (t < b) {
        while (atomicAdd(&g_flag[t], 0) == 0) {}
        __threadfence();
        mine = g_agg[t];
    }
    __syncthreads();
    sdata[t] = mine;
    __syncthreads();
    for (int off = 128; off > 0; off >>= 1) {
        if (t < off) sdata[t] += sdata[t + off];
        __syncthreads();
    }
    int cbase = sdata[0];

    int run = excl + cbase;
#pragma unroll
    for (int j = 0; j < 4; j++) {
        if (base + j < n) g_cursor[base + j] = run;
        run += v[j];
    }
}

__global__ void scatter_kernel(const int* __restrict__ ei, int E) {
    const int4* s4 = (const int4*)ei;
    const int4* d4 = (const int4*)(ei + E);
    int n4 = E >> 2;
    for (int i = blockIdx.x * blockDim.x + threadIdx.x; i < n4;
         i += gridDim.x * blockDim.x) {
        int4 s = s4[i];
        int4 d = d4[i];
        g_sorted_src[atomicAdd(&g_cursor[d.x], 1)] = s.x;
        g_sorted_src[atomicAdd(&g_cursor[d.y], 1)] = s.y;
        g_sorted_src[atomicAdd(&g_cursor[d.z], 1)] = s.z;
        g_sorted_src[atomicAdd(&g_cursor[d.w], 1)] = s.w;
    }
    int t = blockIdx.x * blockDim.x + threadIdx.x;
    if (t < (E & 3)) {
        int e = (n4 << 2) + t;
        g_sorted_src[atomicAdd(&g_cursor[ei[E + e]], 1)] = ei[e];
    }
}

// ---------------------------------------------------------------------------
// K_GATHER: warp-per-destination, HALF-WARP per edge, 6 edges in flight.
// (proven fastest layout: each warp LDG touches 2 random rows)
// beg = cursor[dst-1] (scatter leaves cursor[dst] == segment end).
// Epilogue re-zeroes g_counts/g_flag for the next graph replay.
// ---------------------------------------------------------------------------
__device__ __forceinline__ float dot_f16(float4 q4, uint2 kraw) {
    float2 lo = __half22float2(*(const __half2*)&kraw.x);
    float2 hi = __half22float2(*(const __half2*)&kraw.y);
    return fmaf(q4.x, lo.x, fmaf(q4.y, lo.y, fmaf(q4.z, hi.x, q4.w * hi.y)));
}
__device__ __forceinline__ void acc_f16(float4& acc, float ex, uint2 vraw) {
    float2 lo = __half22float2(*(const __half2*)&vraw.x);
    float2 hi = __half22float2(*(const __half2*)&vraw.y);
    acc.x = fmaf(ex, lo.x, acc.x);
    acc.y = fmaf(ex, lo.y, acc.y);
    acc.z = fmaf(ex, hi.x, acc.z);
    acc.w = fmaf(ex, hi.y, acc.w);
}

__global__ void __launch_bounds__(256) gather_kernel(
    float* __restrict__ out, int n) {
    int warp = (blockIdx.x * blockDim.x + threadIdx.x) >> 5;
    int lane = threadIdx.x & 31;
    if (warp >= n) return;

    int dst  = warp;
    int end  = g_cursor[dst];
    int beg  = (dst > 0) ? g_cursor[dst - 1] : 0;
    int half = lane >> 4;
    int hl   = lane & 15;

    float4 q4 = ((const float4*)(g_q + (size_t)dst * D))[hl];
    q4.x *= 0.125f; q4.y *= 0.125f; q4.z *= 0.125f; q4.w *= 0.125f;

    const uint2* kb = (const uint2*)g_kh;   // 4 fp16 per uint2
    const uint2* vb = (const uint2*)g_vh;

    float4 acc = make_float4(0.f, 0.f, 0.f, 0.f);
    float  s   = 0.f;

    int i = beg;
    for (; i + 5 < end; i += 6) {
        int sA = g_sorted_src[i + half];
        int sB = g_sorted_src[i + 2 + half];
        int sC = g_sorted_src[i + 4 + half];
        uint2 kA = kb[(size_t)sA * (D / 4) + hl];
        uint2 kB = kb[(size_t)sB * (D / 4) + hl];
        uint2 kC = kb[(size_t)sC * (D / 4) + hl];
        uint2 vA = vb[(size_t)sA * (D / 4) + hl];
        uint2 vB = vb[(size_t)sB * (D / 4) + hl];
        uint2 vC = vb[(size_t)sC * (D / 4) + hl];
        float dA = dot_f16(q4, kA);
        float dB = dot_f16(q4, kB);
        float dC = dot_f16(q4, kC);
#pragma unroll
        for (int o = 8; o > 0; o >>= 1) {
            dA += __shfl_xor_sync(0xffffffffu, dA, o);
            dB += __shfl_xor_sync(0xffffffffu, dB, o);
            dC += __shfl_xor_sync(0xffffffffu, dC, o);
        }
        float exA = __expf(dA);
        float exB = __expf(dB);
        float exC = __expf(dC);
        acc_f16(acc, exA, vA);
        acc_f16(acc, exB, vB);
        acc_f16(acc, exC, vC);
        s += exA + exB + exC;
    }
    for (; i + 1 < end; i += 2) {
        int sA = g_sorted_src[i + half];
        uint2 kA = kb[(size_t)sA * (D / 4) + hl];
        uint2 vA = vb[(size_t)sA * (D / 4) + hl];
        float dA = dot_f16(q4, kA);
#pragma unroll
        for (int o = 8; o > 0; o >>= 1)
            dA += __shfl_xor_sync(0xffffffffu, dA, o);
        float exA = __expf(dA);
        acc_f16(acc, exA, vA);
        s += exA;
    }
    if (i < end) {
        int sA = g_sorted_src[i];
        uint2 kA = kb[(size_t)sA * (D / 4) + hl];
        uint2 vA = vb[(size_t)sA * (D / 4) + hl];
        float dA = dot_f16(q4, kA);
#pragma unroll
        for (int o = 8; o > 0; o >>= 1)
            dA += __shfl_xor_sync(0xffffffffu, dA, o);
        float exA = half ? 0.f : __expf(dA);
        acc_f16(acc, exA, vA);
        s += exA;
    }

    acc.x += __shfl_xor_sync(0xffffffffu, acc.x, 16);
    acc.y += __shfl_xor_sync(0xffffffffu, acc.y, 16);
    acc.z += __shfl_xor_sync(0xffffffffu, acc.z, 16);
    acc.w += __shfl_xor_sync(0xffffffffu, acc.w, 16);
    s     += __shfl_xor_sync(0xffffffffu, s, 16);

    float r = 1.0f / (s + 1e-16f);
    float4 sk = ((const float4*)(g_skip + (size_t)dst * D))[hl];
    float4 o;
    o.x = fmaf(acc.x, r, sk.x);
    o.y = fmaf(acc.y, r, sk.y);
    o.z = fmaf(acc.z, r, sk.z);
    o.w = fmaf(acc.w, r, sk.w);
    if (lane < 16)
        ((float4*)(out + (size_t)dst * D))[hl] = o;

    // restore zeroed scratch for the next replay
    if (lane == 0) g_counts[dst] = 0;
    if (lane == 1 && dst < 128) g_flag[dst] = 0;
}

// ---------------------------------------------------------------------------
extern "C" void kernel_launch(void* const* d_in, const int* in_sizes, int n_in,
                              void* d_out, int out_size) {
    const float* x  = (const float*)d_in[0];
    const int*   ei = (const int*)d_in[1];   // int64 in ref -> delivered int32
    // d_in[2] = edge_type (unused by reference)
    const float* Wq = (const float*)d_in[3];
    const float* bq = (const float*)d_in[4];
    const float* Wk = (const float*)d_in[5];
    const float* bk = (const float*)d_in[6];
    const float* Wv = (const float*)d_in[7];
    const float* bv = (const float*)d_in[8];
    const float* Ws = (const float*)d_in[9];
    const float* bs = (const float*)d_in[10];
    float* out = (float*)d_out;

    int n = in_sizes[0] / D;   // 100000
    int E = in_sizes[2];       // 1200000
    if (n > NN) n = NN;
    if (E > EE) E = EE;

    float *gq, *gsk;
    __half *gkh, *gvh;
    cudaGetSymbolAddress((void**)&gq,  g_q);
    cudaGetSymbolAddress((void**)&gkh, g_kh);
    cudaGetSymbolAddress((void**)&gvh, g_vh);
    cudaGetSymbolAddress((void**)&gsk, g_skip);

    int nblk = (n + SCH - 1) / SCH;

    static cudaStream_t s_side = nullptr;
    static cudaEvent_t  ev_fork = nullptr, ev_join = nullptr;
    if (s_side == nullptr) {
        cudaStreamCreateWithFlags(&s_side, cudaStreamNonBlocking);
        cudaEventCreateWithFlags(&ev_fork, cudaEventDisableTiming);
        cudaEventCreateWithFlags(&ev_join, cudaEventDisableTiming);
    }

    // ---- GEMM on side stream, concurrent with CSR build ----
    cudaEventRecord(ev_fork, 0);
    cudaStreamWaitEvent(s_side, ev_fork, 0);
    {
        dim3 grid((n + GR - 1) / GR, 4);
        gemm_one<<<grid, 128, 0, s_side>>>(x, Wq, bq, Wk, bk, Wv, bv, Ws, bs,
                                           gq, gkh, gvh, gsk, n);
    }
    cudaEventRecord(ev_join, s_side);

    // ---- CSR build on default stream (counts pre-zeroed) ----
    hist_kernel<<<(E / 4 + 255) / 256, 256>>>(ei, E);
    scan_fused<<<nblk, 256>>>(n, nblk);
    scatter_kernel<<<(E / 4 + 255) / 256, 256>>>(ei, E);

    // ---- gather (after join); also re-zeroes scratch ----
    cudaStreamWaitEvent(0, ev_join, 0);
    {
        int warps_per_block = 8;
        int blocks = (n + warps_per_block - 1) / warps_per_block;
        gather_kernel<<<blocks, 256>>>(out, n);
    }
}